// round 17
// baseline (speedup 1.0000x reference)
#include <cuda_runtime.h>
#include <math.h>

// ---------------- static scratch ----------------
__device__ __align__(16) float g_bufA[16777216];
__device__ __align__(16) float g_bufB[8388608];
__device__ __align__(16) float g_wt0[3*49*32];
__device__ __align__(16) float g_wt1[32*9*64];
__device__ __align__(16) float g_wt2[64*9*128];
__device__ __align__(16) float g_wt3[128*9*256];
__device__ __align__(16) float g_wt4[256*9*128];
__device__ __align__(16) float g_wt5[128*9*64];
__device__ __align__(16) float g_wt6[64*9*32];
__device__ __align__(16) float g_wt7[32*49*4];
__device__ float g_segsum[96];
__device__ float g_segcnt[32];
__device__ float g_ps[5632];     // per-plane sum   (L0..L6)
__device__ float g_pq[5632];     // per-plane sumsq

typedef unsigned long long ull;

// ---------------- f32x2 packed helpers ----------------
__device__ __forceinline__ ull pack2(float v) {
    ull r;
    asm("mov.b64 %0, {%1, %1};" : "=l"(r) : "f"(v));
    return r;
}
__device__ __forceinline__ void fma2(ull& d, ull a, ull b) {
    asm("fma.rn.f32x2 %0, %1, %2, %0;" : "+l"(d) : "l"(a), "l"(b));
}
__device__ __forceinline__ float2 unpack2(ull v) {
    float2 f;
    asm("mov.b64 {%0, %1}, %2;" : "=f"(f.x), "=f"(f.y) : "l"(v));
    return f;
}

// ---------------- cp.async helpers ----------------
__device__ __forceinline__ unsigned s2u(const void* p) {
    return (unsigned)__cvta_generic_to_shared(p);
}
__device__ __forceinline__ void cp4(unsigned dst, const float* src, bool pred) {
    asm volatile("cp.async.ca.shared.global [%0], [%1], 4, %2;" ::
                 "r"(dst), "l"(src), "r"(pred ? 4u : 0u));
}
__device__ __forceinline__ void cp16(unsigned dst, const float* src) {
    asm volatile("cp.async.cg.shared.global [%0], [%1], 16;" ::
                 "r"(dst), "l"(src));
}
__device__ __forceinline__ void cp16z(unsigned dst, const float* src, unsigned sz) {
    asm volatile("cp.async.cg.shared.global [%0], [%1], 16, %2;" ::
                 "r"(dst), "l"(src), "r"(sz));
}
__device__ __forceinline__ void cp_commit() {
    asm volatile("cp.async.commit_group;" ::: "memory");
}
template <int N>
__device__ __forceinline__ void cp_wait() {
    asm volatile("cp.async.wait_group %0;" :: "n"(N) : "memory");
}

// ---------------- fused weight prep + bin zero ----------------
__global__ void k_prep(const float* __restrict__ w0, const float* __restrict__ w1,
                       const float* __restrict__ w2, const float* __restrict__ w3,
                       const float* __restrict__ w4, const float* __restrict__ w5,
                       const float* __restrict__ w6, const float* __restrict__ w7,
                       float* o0, float* o1, float* o2, float* o3,
                       float* o4, float* o5, float* o6, float* o7,
                       float* segsum, float* segcnt, float* ps, float* pq) {
    int idx = blockIdx.x * 256 + threadIdx.x;
    switch (blockIdx.y) {
    case 0: if (idx < 32*3*49)   { int o=idx/147,  r=idx%147,  i=r/49, k=r%49; o0[(i*49+k)*32+o]=w0[idx]; } break;
    case 1: if (idx < 64*32*9)   { int o=idx/288,  r=idx%288,  i=r/9,  k=r%9;  o1[(i*9+k)*64+o]=w1[idx]; } break;
    case 2: if (idx < 128*64*9)  { int o=idx/576,  r=idx%576,  i=r/9,  k=r%9;  o2[(i*9+k)*128+o]=w2[idx]; } break;
    case 3: if (idx < 256*128*9) { int o=idx/1152, r=idx%1152, i=r/9,  k=r%9;  o3[(i*9+k)*256+o]=w3[idx]; } break;
    case 4: if (idx < 256*128*9) { int i=idx/1152, r=idx%1152, o=r/9,  k=r%9;  o4[(i*9+k)*128+o]=w4[idx]; } break;
    case 5: if (idx < 128*64*9)  { int i=idx/576,  r=idx%576,  o=r/9,  k=r%9;  o5[(i*9+k)*64+o]=w5[idx]; } break;
    case 6: if (idx < 64*32*9)   { int i=idx/288,  r=idx%288,  o=r/9,  k=r%9;  o6[(i*9+k)*32+o]=w6[idx]; } break;
    case 7: if (idx < 32*49*4)   { int p=idx>>2, o=idx&3; int i=p/49, k=p%49;
                                   o7[idx] = (o < 3) ? w7[(o*32+i)*49+k] : 0.f; } break;
    case 8: if (idx < 96) segsum[idx] = 0.f;
            if (idx < 32) segcnt[idx] = 0.f;
            if (idx < 5632) { ps[idx] = 0.f; pq[idx] = 0.f; }
            break;
    }
}

// ---------------- layer 0: reflect-pad 7x7 conv 3->32 + fused stats ----------
__global__ void __launch_bounds__(256)
k_conv7_l0(const float* __restrict__ x, const float* __restrict__ wt,
           const float* __restrict__ bias, float* __restrict__ out,
           float* __restrict__ ps, float* __restrict__ pq) {
    __shared__ __align__(16) float s_w[3 * 49 * 32];
    __shared__ __align__(16) float s_in[3 * 22 * 36];
    const int tid = threadIdx.x;
    const int wz = tid >> 5;
    const int lane = tid & 31;
    const int og = lane & 3;
    const int pg = (lane >> 2) & 3;
    const int r = lane >> 4;
    const int n = blockIdx.z;
    const int oy0 = blockIdx.y * 16, ox0 = blockIdx.x * 16;

    for (int i = tid; i < 3 * 49 * 32; i += 256) s_w[i] = wt[i];
    const float* xp = x + (size_t)n * 3 * 65536;
    for (int i = tid; i < 3 * 484; i += 256) {
        int ic = i / 484, rr = (i % 484) / 22, cc = i % 22;
        int iy = oy0 + rr - 3, ix = ox0 + cc - 3;
        iy = iy < 0 ? -iy : (iy > 255 ? 510 - iy : iy);
        ix = ix < 0 ? -ix : (ix > 255 ? 510 - ix : ix);
        s_in[ic * 792 + rr * 36 + cc] = xp[ic * 65536 + iy * 256 + ix];
    }
    __syncthreads();

    ull acc[4][4];
#pragma unroll
    for (int d = 0; d < 4; d++)
#pragma unroll
        for (int j = 0; j < 4; j++) acc[d][j] = 0ull;

#pragma unroll 1
    for (int ic = 0; ic < 3; ic++) {
        const float* si = s_in + ic * 792 + 4 * pg;
        const float* wic = s_w + ic * 49 * 32 + og * 8;
#pragma unroll 1
        for (int ky = 0; ky < 7; ky++) {
            const float4* rv = (const float4*)(si + (2 * wz + r + ky) * 36);
            float4 q0 = rv[0], q1 = rv[1], q2 = rv[2];
            ull u[10];
            u[0] = pack2(q0.x); u[1] = pack2(q0.y); u[2] = pack2(q0.z);
            u[3] = pack2(q0.w); u[4] = pack2(q1.x); u[5] = pack2(q1.y);
            u[6] = pack2(q1.z); u[7] = pack2(q1.w); u[8] = pack2(q2.x);
            u[9] = pack2(q2.y);
            const float* wky = wic + ky * 7 * 32;
#pragma unroll
            for (int kx = 0; kx < 7; kx++) {
                const ulonglong2* wp = (const ulonglong2*)(wky + kx * 32);
                ulonglong2 w2 = wp[0], w3 = wp[1];
#pragma unroll
                for (int d = 0; d < 4; d++) {
                    ull v = u[kx + d];
                    fma2(acc[d][0], v, w2.x);
                    fma2(acc[d][1], v, w2.y);
                    fma2(acc[d][2], v, w3.x);
                    fma2(acc[d][3], v, w3.y);
                }
            }
        }
    }

    const int oy = oy0 + 2 * wz + r;
    const int ox = ox0 + 4 * pg;
    float* obase = out + (size_t)n * 32 * 65536 + (size_t)(og * 8) * 65536 +
                   (size_t)oy * 256 + ox;
    float ssum[8], ssq[8];
#pragma unroll
    for (int k = 0; k < 8; k++) { ssum[k] = 0.f; ssq[k] = 0.f; }
#pragma unroll
    for (int j = 0; j < 4; j++) {
        float2 p0 = unpack2(acc[0][j]);
        float2 p1 = unpack2(acc[1][j]);
        float2 p2 = unpack2(acc[2][j]);
        float2 p3 = unpack2(acc[3][j]);
        float blo = bias[og * 8 + 2 * j];
        float bhi = bias[og * 8 + 2 * j + 1];
        float v0 = p0.x + blo, v1 = p1.x + blo, v2 = p2.x + blo, v3 = p3.x + blo;
        float w0 = p0.y + bhi, w1 = p1.y + bhi, w2 = p2.y + bhi, w3 = p3.y + bhi;
        *(float4*)(obase + (size_t)(2 * j) * 65536) = make_float4(v0, v1, v2, v3);
        *(float4*)(obase + (size_t)(2 * j + 1) * 65536) = make_float4(w0, w1, w2, w3);
        ssum[2 * j] += v0 + v1 + v2 + v3;
        ssq[2 * j] += v0 * v0 + v1 * v1 + v2 * v2 + v3 * v3;
        ssum[2 * j + 1] += w0 + w1 + w2 + w3;
        ssq[2 * j + 1] += w0 * w0 + w1 * w1 + w2 * w2 + w3 * w3;
    }
#pragma unroll
    for (int o = 4; o < 32; o <<= 1)
#pragma unroll
        for (int k = 0; k < 8; k++) {
            ssum[k] += __shfl_xor_sync(0xffffffffu, ssum[k], o);
            ssq[k] += __shfl_xor_sync(0xffffffffu, ssq[k], o);
        }
    if (lane < 4) {
        int base = n * 32 + lane * 8;
#pragma unroll
        for (int k = 0; k < 8; k++) {
            atomicAdd(&ps[base + k], ssum[k]);
            atomicAdd(&pq[base + k], ssq[k]);
        }
    }
}

// ---------------- 3x3 stride-2 conv + fused stats ----------------
template <int IC, int OC, int ICC, int OCB>
__global__ void __launch_bounds__(256, 2)
k_conv3s2(const float* __restrict__ in, const float* __restrict__ wt,
          const float* __restrict__ bias, float* __restrict__ out,
          float* __restrict__ ps, float* __restrict__ pq, int psOff,
          int Hin, int Win, int Hout, int Wout) {
    const int PIN = 33 * 36;
    const int NOG = OCB / 8;
    const int RPT = (OCB == 64) ? 2 : 1;
    extern __shared__ float smem[];
    float* s_w  = smem;
    float* s_in = s_w + 2 * ICC * 9 * OCB;

    const int tid = threadIdx.x;
    const int wz = tid >> 5;
    const int lane = tid & 31;
    const int og = lane % NOG;
    const int rest = lane / NOG;
    const int pg = rest & 3;
    const int r2 = rest >> 2;
    const int z = blockIdx.z;
    const int n = z / (OC / OCB);
    const int oc0 = (z % (OC / OCB)) * OCB;
    const int oy0 = blockIdx.y * 16, ox0 = blockIdx.x * 16;
    const int iy0 = 2 * oy0 - 1;
    const int ixa = 2 * ox0 - 4;

    const float* inp = in + (size_t)n * IC * Hin * Win;

    auto prefetch = [&](int st, int b) {
        int ic0 = st * ICC;
        float* bw = s_w + b * (ICC * 9 * OCB);
        float* bi = s_in + b * (ICC * PIN);
        for (int i = tid; i < ICC * 33 * 9; i += 256) {
            int icl = i / 297;
            int rr = i % 297;
            int rw = rr / 9, c9 = rr % 9;
            int iy = iy0 + rw;
            int sx = ixa + 4 * c9;
            bool ok = ((unsigned)iy < (unsigned)Hin) && (sx >= 0);
            unsigned sz = ok ? 16u : 0u;
            const float* src = inp + (size_t)(ic0 + icl) * Hin * Win +
                               (ok ? iy * Win + sx : 0);
            cp16z(s2u(bi + icl * PIN + rw * 36 + 4 * c9), src, sz);
        }
        const float* wsrc = wt + (size_t)ic0 * 9 * OC + oc0;
        for (int i = tid; i < ICC * 9 * (OCB / 4); i += 256) {
            int p = i / (OCB / 4), c = i % (OCB / 4);
            cp16(s2u(bw + p * OCB + 4 * c), wsrc + (size_t)p * OC + 4 * c);
        }
    };

    ull acc[RPT][4][4];
#pragma unroll
    for (int r = 0; r < RPT; r++)
#pragma unroll
        for (int c = 0; c < 4; c++)
#pragma unroll
            for (int j = 0; j < 4; j++) acc[r][c][j] = 0ull;

    prefetch(0, 0);
    cp_commit();
    const int NS = IC / ICC;
    for (int s = 0; s < NS; s++) {
        if (s + 1 < NS) { prefetch(s + 1, (s + 1) & 1); cp_commit(); cp_wait<1>(); }
        else cp_wait<0>();
        __syncthreads();
        const float* bi = s_in + (s & 1) * (ICC * PIN);
        const float* bw = s_w + (s & 1) * (ICC * 9 * OCB);
#pragma unroll 1
        for (int icl = 0; icl < ICC; icl++) {
            const float* rb = bi + icl * PIN + 8 * pg;
            const float* wb = bw + icl * 9 * OCB + og * 8;
#pragma unroll
            for (int ky = 0; ky < 3; ky++) {
                ull u[RPT][9];
#pragma unroll
                for (int r = 0; r < RPT; r++) {
                    int rowr = (RPT == 2) ? r : r2;
                    const float4* rv = (const float4*)(rb + (4 * wz + 2 * rowr + ky) * 36);
                    float4 a0 = rv[0], a1 = rv[1], a2 = rv[2];
                    u[r][0] = pack2(a0.w); u[r][1] = pack2(a1.x); u[r][2] = pack2(a1.y);
                    u[r][3] = pack2(a1.z); u[r][4] = pack2(a1.w); u[r][5] = pack2(a2.x);
                    u[r][6] = pack2(a2.y); u[r][7] = pack2(a2.z); u[r][8] = pack2(a2.w);
                }
#pragma unroll
                for (int kx = 0; kx < 3; kx++) {
                    const ulonglong2* wp = (const ulonglong2*)(wb + (3 * ky + kx) * OCB);
                    ulonglong2 wa = wp[0], wb2 = wp[1];
#pragma unroll
                    for (int c = 0; c < 4; c++)
#pragma unroll
                        for (int r = 0; r < RPT; r++) {
                            ull v = u[r][2 * c + kx];
                            fma2(acc[r][c][0], v, wa.x);
                            fma2(acc[r][c][1], v, wa.y);
                            fma2(acc[r][c][2], v, wb2.x);
                            fma2(acc[r][c][3], v, wb2.y);
                        }
                }
            }
        }
        __syncthreads();
    }

    const int ox = ox0 + 4 * pg;
    const size_t cs = (size_t)Hout * Wout;
    float ssum[8], ssq[8];
#pragma unroll
    for (int k = 0; k < 8; k++) { ssum[k] = 0.f; ssq[k] = 0.f; }
#pragma unroll
    for (int r = 0; r < RPT; r++) {
        int rowr = (RPT == 2) ? r : r2;
        int oy = oy0 + 2 * wz + rowr;
        float* obase = out + (size_t)(n * OC + oc0 + og * 8) * cs + (size_t)oy * Wout + ox;
#pragma unroll
        for (int j = 0; j < 4; j++) {
            float2 p0 = unpack2(acc[r][0][j]);
            float2 p1 = unpack2(acc[r][1][j]);
            float2 p2 = unpack2(acc[r][2][j]);
            float2 p3 = unpack2(acc[r][3][j]);
            float blo = bias[oc0 + og * 8 + 2 * j];
            float bhi = bias[oc0 + og * 8 + 2 * j + 1];
            float v0 = p0.x + blo, v1 = p1.x + blo, v2 = p2.x + blo, v3 = p3.x + blo;
            float w0 = p0.y + bhi, w1 = p1.y + bhi, w2 = p2.y + bhi, w3 = p3.y + bhi;
            *(float4*)(obase + (size_t)(2 * j) * cs) = make_float4(v0, v1, v2, v3);
            *(float4*)(obase + (size_t)(2 * j + 1) * cs) = make_float4(w0, w1, w2, w3);
            ssum[2 * j] += v0 + v1 + v2 + v3;
            ssq[2 * j] += v0 * v0 + v1 * v1 + v2 * v2 + v3 * v3;
            ssum[2 * j + 1] += w0 + w1 + w2 + w3;
            ssq[2 * j + 1] += w0 * w0 + w1 * w1 + w2 * w2 + w3 * w3;
        }
    }
#pragma unroll
    for (int o = NOG; o < 32; o <<= 1)
#pragma unroll
        for (int k = 0; k < 8; k++) {
            ssum[k] += __shfl_xor_sync(0xffffffffu, ssum[k], o);
            ssq[k] += __shfl_xor_sync(0xffffffffu, ssq[k], o);
        }
    if (lane < NOG) {
        int base = psOff + n * OC + oc0 + lane * 8;
#pragma unroll
        for (int k = 0; k < 8; k++) {
            atomicAdd(&ps[base + k], ssum[k]);
            atomicAdd(&pq[base + k], ssq[k]);
        }
    }
}

// ---------------- convT: pitched I/O + fused stats ----------------
__device__ __forceinline__ void tap8(ull* A, ull* B, ull va, ull vb,
                                     const ulonglong2* wp) {
    ulonglong2 w0 = wp[0], w1 = wp[1];
    fma2(A[0], va, w0.x); fma2(A[1], va, w0.y);
    fma2(A[2], va, w1.x); fma2(A[3], va, w1.y);
    fma2(B[0], vb, w0.x); fma2(B[1], vb, w0.y);
    fma2(B[2], vb, w1.x); fma2(B[3], vb, w1.y);
}

template <int IC, int OC, int ICC>
__global__ void __launch_bounds__(256, 2)
k_convT(const float* __restrict__ in, const float* __restrict__ wt,
        const float* __restrict__ bias, float* __restrict__ out,
        float* __restrict__ ps, float* __restrict__ pq, int psOff,
        int Hin, int Win, int pitchIn, int Hout, int Wout, int pitchOut) {
    const int OCB = 8;
    const int PIN = 17 * 36;
    extern __shared__ float smem[];
    float* s_w  = smem;
    float* s_in = s_w + 2 * ICC * 9 * OCB;

    const int tid = threadIdx.x;
    const int ty = tid >> 4;
    const int tx = tid & 15;
    const int z = blockIdx.z;
    const int n = z / (OC / OCB);
    const int oc0 = (z % (OC / OCB)) * OCB;
    const int oy0 = blockIdx.y * 32, ox0 = blockIdx.x * 64;
    const int iy0 = oy0 >> 1, ix0 = ox0 >> 1;

    const float* inp = in + (size_t)n * IC * Hin * pitchIn;

    auto prefetch = [&](int st, int b) {
        int ic0 = st * ICC;
        float* bw = s_w + b * (ICC * 9 * OCB);
        float* bi = s_in + b * (ICC * PIN);
        for (int i = tid; i < ICC * 153; i += 256) {
            int icl = i / 153, rr = i % 153;
            int r = rr / 9, c9 = rr % 9;
            int iy = iy0 + r;
            int sx = ix0 + 4 * c9;
            int vb = (iy < Hin) ? (Win - sx) : 0;
            unsigned sz = vb >= 4 ? 16u : (vb > 0 ? (unsigned)(4 * vb) : 0u);
            const float* src = inp + (size_t)(ic0 + icl) * Hin * pitchIn +
                               (sz ? iy * pitchIn + sx : 0);
            cp16z(s2u(bi + icl * PIN + r * 36 + 4 * c9), src, sz);
        }
        const float* wsrc = wt + (size_t)ic0 * 9 * OC + oc0;
        for (int i = tid; i < ICC * 9 * 2; i += 256) {
            int p = i >> 1, c = i & 1;
            cp16(s2u(bw + p * OCB + 4 * c), wsrc + (size_t)p * OC + 4 * c);
        }
    };

    ull acc[2][4][4];
#pragma unroll
    for (int b2 = 0; b2 < 2; b2++)
#pragma unroll
        for (int c = 0; c < 4; c++)
#pragma unroll
            for (int j = 0; j < 4; j++) acc[b2][c][j] = 0ull;

    prefetch(0, 0);
    cp_commit();
    const int NS = IC / ICC;
    for (int s = 0; s < NS; s++) {
        if (s + 1 < NS) { prefetch(s + 1, (s + 1) & 1); cp_commit(); cp_wait<1>(); }
        else cp_wait<0>();
        __syncthreads();
        const float* bi = s_in + (s & 1) * (ICC * PIN);
        const float* bw = s_w + (s & 1) * (ICC * 9 * OCB);
#pragma unroll 2
        for (int icl = 0; icl < ICC; icl++) {
            const float* sp = bi + icl * PIN + ty * 36 + tx;
            ull a00 = pack2(sp[0]);
            ull a01 = pack2(sp[1]);
            ull a10 = pack2(sp[36]);
            ull a11 = pack2(sp[37]);
            ull b00 = pack2(sp[16]);
            ull b01 = pack2(sp[17]);
            ull b10 = pack2(sp[52]);
            ull b11 = pack2(sp[53]);
            const ulonglong2* wp = (const ulonglong2*)(bw + icl * 9 * OCB);
            tap8(acc[0][3], acc[1][3], a11, b11, wp + 0);
            tap8(acc[0][2], acc[1][2], a10, b10, wp + 2);
            tap8(acc[0][3], acc[1][3], a10, b10, wp + 4);
            tap8(acc[0][1], acc[1][1], a01, b01, wp + 6);
            tap8(acc[0][0], acc[1][0], a00, b00, wp + 8);
            tap8(acc[0][1], acc[1][1], a00, b00, wp + 10);
            tap8(acc[0][3], acc[1][3], a01, b01, wp + 12);
            tap8(acc[0][2], acc[1][2], a00, b00, wp + 14);
            tap8(acc[0][3], acc[1][3], a00, b00, wp + 16);
        }
        __syncthreads();
    }

    const size_t cs = (size_t)Hout * pitchOut;
    float ssum[8], ssq[8];
#pragma unroll
    for (int k = 0; k < 8; k++) { ssum[k] = 0.f; ssq[k] = 0.f; }
#pragma unroll
    for (int b2 = 0; b2 < 2; b2++) {
        int ye = oy0 + 2 * ty;
        int xe = ox0 + 2 * (tx + b2 * 16);
        bool y0v = ye < Hout, y1v = (ye + 1) < Hout;
        bool x0v = xe < Wout, x1v = (xe + 1) < Wout;
#pragma unroll
        for (int j = 0; j < 4; j++) {
            float bz0 = bias[oc0 + 2 * j], bz1 = bias[oc0 + 2 * j + 1];
            float* op0 = out + (size_t)(n * OC + oc0 + 2 * j) * cs;
            float* op1 = op0 + cs;
            float2 a;
#define EMIT(CLS, OFF, COND)                                               \
            if (COND) {                                                    \
                a = unpack2(acc[b2][CLS][j]);                              \
                float vx = a.x + bz0, vy = a.y + bz1;                      \
                op0[OFF] = vx; op1[OFF] = vy;                              \
                ssum[2 * j] += vx; ssq[2 * j] += vx * vx;                  \
                ssum[2 * j + 1] += vy; ssq[2 * j + 1] += vy * vy;          \
            }
            EMIT(0, ye * pitchOut + xe, y0v && x0v)
            EMIT(1, ye * pitchOut + xe + 1, y0v && x1v)
            EMIT(2, (ye + 1) * pitchOut + xe, y1v && x0v)
            EMIT(3, (ye + 1) * pitchOut + xe + 1, y1v && x1v)
#undef EMIT
        }
    }
#pragma unroll
    for (int o = 1; o < 32; o <<= 1)
#pragma unroll
        for (int k = 0; k < 8; k++) {
            ssum[k] += __shfl_xor_sync(0xffffffffu, ssum[k], o);
            ssq[k] += __shfl_xor_sync(0xffffffffu, ssq[k], o);
        }
    if ((tid & 31) == 0) {
        int base = psOff + n * OC + oc0;
#pragma unroll
        for (int k = 0; k < 8; k++) {
            atomicAdd(&ps[base + k], ssum[k]);
            atomicAdd(&pq[base + k], ssq[k]);
        }
    }
}

// ---------------- layer 7: 7x7 conv 32->3 + tanh + fused segment accumulate ----
__global__ void __launch_bounds__(256, 2)
k_conv7_l7(const float* __restrict__ act, const float* __restrict__ wt,
           const float* __restrict__ bias, const int* __restrict__ inst,
           float* __restrict__ gsum, float* __restrict__ gcnt) {
    extern __shared__ float smem[];
    float* s_w  = smem;
    float* s_in = s_w + 6272;
    __shared__ float ssb[96];
    __shared__ float scb[32];

    const int H = 249;
    const int PLANE = 63744;
    const int tid = threadIdx.x;
    const int tx = tid & 7;
    const int ty = tid >> 3;
    const int n = blockIdx.z;
    const int oy0 = blockIdx.y * 32, ox0 = blockIdx.x * 32;

    for (int i = tid; i < 6272; i += 256) s_w[i] = wt[i];
    if (tid < 96) ssb[tid] = 0.f;
    if (tid < 32) scb[tid] = 0.f;

    const float* ap = act + (size_t)n * 32 * PLANE;
    auto prefetch = [&](int st, int b) {
        float* bi = s_in + b * (4 * 1520);
        int ic0 = st * 4;
        for (int i = tid; i < 4 * 1444; i += 256) {
            int icl = i / 1444, rr = i % 1444;
            int r = rr / 38, c = rr % 38;
            int iy = oy0 + r - 3, ix = ox0 + c - 3;
            iy = iy < 0 ? -iy : (iy > 248 ? 496 - iy : iy);
            ix = ix < 0 ? -ix : (ix > 248 ? 496 - ix : ix);
            cp4(s2u(bi + icl * 1520 + r * 40 + c),
                ap + (size_t)(ic0 + icl) * PLANE + iy * 256 + ix, true);
        }
    };

    ull acc[4][2];
#pragma unroll
    for (int p = 0; p < 4; p++) { acc[p][0] = 0ull; acc[p][1] = 0ull; }

    prefetch(0, 0);
    cp_commit();
    for (int s = 0; s < 8; s++) {
        if (s < 7) { prefetch(s + 1, (s + 1) & 1); cp_commit(); cp_wait<1>(); }
        else cp_wait<0>();
        __syncthreads();
        const float* bi = s_in + (s & 1) * (4 * 1520);
#pragma unroll 1
        for (int icl = 0; icl < 4; icl++) {
            const float* wic = s_w + (s * 4 + icl) * 196;
            const float* si = bi + icl * 1520;
#pragma unroll 1
            for (int ky = 0; ky < 7; ky++) {
                const float4* rv = (const float4*)(si + (ty + ky) * 40 + 4 * tx);
                float4 q0 = rv[0], q1 = rv[1], q2 = rv[2];
                ull u[10];
                u[0] = pack2(q0.x); u[1] = pack2(q0.y); u[2] = pack2(q0.z);
                u[3] = pack2(q0.w); u[4] = pack2(q1.x); u[5] = pack2(q1.y);
                u[6] = pack2(q1.z); u[7] = pack2(q1.w); u[8] = pack2(q2.x);
                u[9] = pack2(q2.y);
                const ulonglong2* wp = (const ulonglong2*)(wic + ky * 28);
#pragma unroll
                for (int kx = 0; kx < 7; kx++) {
                    ulonglong2 w2 = wp[kx];
#pragma unroll
                    for (int d = 0; d < 4; d++) {
                        fma2(acc[d][0], u[kx + d], w2.x);
                        fma2(acc[d][1], u[kx + d], w2.y);
                    }
                }
            }
        }
        __syncthreads();
    }

    float b0 = bias[0], b1 = bias[1], b2 = bias[2];
    const int* ip = inst + (size_t)n * 62001;
    int oy = oy0 + ty;
    if (oy < H) {
#pragma unroll
        for (int d = 0; d < 4; d++) {
            int ox = ox0 + 4 * tx + d;
            if (ox < H) {
                float2 a0 = unpack2(acc[d][0]);
                float2 a1 = unpack2(acc[d][1]);
                float t0 = tanhf(a0.x + b0);
                float t1 = tanhf(a0.y + b1);
                float t2 = tanhf(a1.x + b2);
                int id = ip[oy * 249 + ox];
                atomicAdd(&ssb[id * 3 + 0], t0);
                atomicAdd(&ssb[id * 3 + 1], t1);
                atomicAdd(&ssb[id * 3 + 2], t2);
                atomicAdd(&scb[id], 1.f);
            }
        }
    }
    __syncthreads();
    if (tid < 96) atomicAdd(&gsum[tid], ssb[tid]);
    if (tid < 32) atomicAdd(&gcnt[tid], scb[tid]);
}

// ---------------- instance-norm finalize + normalize (contiguous) ----------------
__global__ void k_instat_f(float* __restrict__ x, const float* __restrict__ ps,
                           const float* __restrict__ pq, int off, int HW) {
    int p = blockIdx.x;
    float* xp = x + (size_t)p * HW;
    float s = ps[off + p], q = pq[off + p];
    float m = s / HW;
    float var = q / HW - m * m;
    float rs = rsqrtf(fmaxf(var, 0.f) + 1e-5f);
    float sf = -m * rs;
    float4* x4 = (float4*)xp;
    int n4 = HW >> 2;
    for (int i = threadIdx.x; i < n4; i += 256) {
        float4 v = x4[i];
        v.x = fmaxf(fmaf(v.x, rs, sf), 0.f);
        v.y = fmaxf(fmaf(v.y, rs, sf), 0.f);
        v.z = fmaxf(fmaf(v.z, rs, sf), 0.f);
        v.w = fmaxf(fmaf(v.w, rs, sf), 0.f);
        x4[i] = v;
    }
}

// ---------------- instance-norm finalize + normalize (pitched) ----------------
__global__ void k_instat_fp(float* __restrict__ x, const float* __restrict__ ps,
                            const float* __restrict__ pq, int off,
                            int H, int W, int pitch) {
    int p = blockIdx.x;
    float* xp = x + (size_t)p * H * pitch;
    float s = ps[off + p], q = pq[off + p];
    float inv = 1.f / (float)(H * W);
    float m = s * inv;
    float var = q * inv - m * m;
    float rs = rsqrtf(fmaxf(var, 0.f) + 1e-5f);
    float sf = -m * rs;
    const int total = H * pitch;
    const int mask = pitch - 1;
    for (int i = threadIdx.x; i < total; i += 256) {
        if ((i & mask) < W)
            xp[i] = fmaxf(fmaf(xp[i], rs, sf), 0.f);
    }
}

// ---------------- segment mean broadcast ----------------
__global__ void k_segbcast(const int* __restrict__ inst, const float* __restrict__ gsum,
                           const float* __restrict__ gcnt, float* __restrict__ out) {
    const int P = 62001, T = 8 * 3 * P;
    for (int i = blockIdx.x * blockDim.x + threadIdx.x; i < T; i += gridDim.x * blockDim.x) {
        int n = i / (3 * P), r = i % (3 * P);
        int c = r / P, p = r % P;
        int id = inst[n * P + p];
        out[i] = gsum[id * 3 + c] / fmaxf(gcnt[id], 1.f);
    }
}

// ---------------- launch ----------------
extern "C" void kernel_launch(void* const* d_in, const int* in_sizes, int n_in,
                              void* d_out, int out_size) {
    const float* x = (const float*)d_in[0];
    const int* inst = (const int*)d_in[1];
    const float* w[8];
    const float* b[8];
    for (int i = 0; i < 8; i++) {
        w[i] = (const float*)d_in[2 + 2 * i];
        b[i] = (const float*)d_in[3 + 2 * i];
    }
    float* out = (float*)d_out;

    float *A, *B, *PS, *PQ;
    float *WT0, *WT1, *WT2, *WT3, *WT4, *WT5, *WT6, *WT7, *SS, *SN;
    cudaGetSymbolAddress((void**)&A, g_bufA);
    cudaGetSymbolAddress((void**)&B, g_bufB);
    cudaGetSymbolAddress((void**)&PS, g_ps);
    cudaGetSymbolAddress((void**)&PQ, g_pq);
    cudaGetSymbolAddress((void**)&WT0, g_wt0);
    cudaGetSymbolAddress((void**)&WT1, g_wt1);
    cudaGetSymbolAddress((void**)&WT2, g_wt2);
    cudaGetSymbolAddress((void**)&WT3, g_wt3);
    cudaGetSymbolAddress((void**)&WT4, g_wt4);
    cudaGetSymbolAddress((void**)&WT5, g_wt5);
    cudaGetSymbolAddress((void**)&WT6, g_wt6);
    cudaGetSymbolAddress((void**)&WT7, g_wt7);
    cudaGetSymbolAddress((void**)&SS, g_segsum);
    cudaGetSymbolAddress((void**)&SN, g_segcnt);

    // plane-bin offsets: L0:0 L1:256 L2:768 L3:1792 L4:3840 L5:4864 L6:5376
    const int SM_C64 = (2*8*9*64 + 2*8*33*36) * 4;
    const int SM_C32 = (2*8*9*32 + 2*8*33*36) * 4;
    const int SM_T = (2*8*9*8 + 2*8*17*36) * 4;
    const int SM_L7 = (6272 + 2*4*1520) * 4;

    cudaFuncSetAttribute(k_conv3s2<32, 64, 8, 64>,  cudaFuncAttributeMaxDynamicSharedMemorySize, SM_C64);
    cudaFuncSetAttribute(k_conv3s2<64, 128, 8, 64>, cudaFuncAttributeMaxDynamicSharedMemorySize, SM_C64);
    cudaFuncSetAttribute(k_conv3s2<128, 256, 8, 32>,cudaFuncAttributeMaxDynamicSharedMemorySize, SM_C32);
    cudaFuncSetAttribute(k_convT<256, 128, 8>,  cudaFuncAttributeMaxDynamicSharedMemorySize, SM_T);
    cudaFuncSetAttribute(k_convT<128, 64, 8>,   cudaFuncAttributeMaxDynamicSharedMemorySize, SM_T);
    cudaFuncSetAttribute(k_convT<64, 32, 8>,    cudaFuncAttributeMaxDynamicSharedMemorySize, SM_T);
    cudaFuncSetAttribute(k_conv7_l7,            cudaFuncAttributeMaxDynamicSharedMemorySize, SM_L7);

    // weight prep + bin zero
    k_prep<<<dim3(1152, 9), 256>>>(w[0], w[1], w[2], w[3], w[4], w[5], w[6], w[7],
                                   WT0, WT1, WT2, WT3, WT4, WT5, WT6, WT7,
                                   SS, SN, PS, PQ);
    // layer 0
    k_conv7_l0<<<dim3(16, 16, 8), 256>>>(x, WT0, b[0], A, PS, PQ);
    k_instat_f<<<8 * 32, 256>>>(A, PS, PQ, 0, 65536);
    // layers 1-3
    k_conv3s2<32, 64, 8, 64><<<dim3(8, 8, 8), 256, SM_C64>>>(A, WT1, b[1], B, PS, PQ, 256,
                                                             256, 256, 128, 128);
    k_instat_f<<<8 * 64, 256>>>(B, PS, PQ, 256, 16384);
    k_conv3s2<64, 128, 8, 64><<<dim3(4, 4, 16), 256, SM_C64>>>(B, WT2, b[2], A, PS, PQ, 768,
                                                               128, 128, 64, 64);
    k_instat_f<<<8 * 128, 256>>>(A, PS, PQ, 768, 4096);
    k_conv3s2<128, 256, 8, 32><<<dim3(2, 2, 64), 256, SM_C32>>>(A, WT3, b[3], B, PS, PQ, 1792,
                                                                64, 64, 32, 32);
    k_instat_f<<<8 * 256, 256>>>(B, PS, PQ, 1792, 1024);
    // layers 4-6 (transposed conv, pitched outputs)
    k_convT<256, 128, 8><<<dim3(1, 2, 128), 256, SM_T>>>(B, WT4, b[4], A, PS, PQ, 3840,
                                                         32, 32, 32, 63, 63, 64);
    k_instat_fp<<<8 * 128, 256>>>(A, PS, PQ, 3840, 63, 63, 64);
    k_convT<128, 64, 8><<<dim3(2, 4, 64), 256, SM_T>>>(A, WT5, b[5], B, PS, PQ, 4864,
                                                       63, 63, 64, 125, 125, 128);
    k_instat_fp<<<8 * 64, 256>>>(B, PS, PQ, 4864, 125, 125, 128);
    k_convT<64, 32, 8><<<dim3(4, 8, 32), 256, SM_T>>>(B, WT6, b[6], A, PS, PQ, 5376,
                                                      125, 125, 128, 249, 249, 256);
    k_instat_fp<<<8 * 32, 256>>>(A, PS, PQ, 5376, 249, 249, 256);
    // layer 7 with fused segment accumulation
    k_conv7_l7<<<dim3(8, 8, 8), 256, SM_L7>>>(A, WT7, b[7], inst, SS, SN);
    // broadcast means
    k_segbcast<<<2048, 256>>>(inst, SS, SN, out);
}